// round 9
// baseline (speedup 1.0000x reference)
#include <cuda_runtime.h>
#include <math.h>

// Shapes: H=24, Mdim=48, C=8, P=8
// u[c] = term1 + term2 + term3 + term4 (see previous rounds)

#define HH 24
#define MD 48
#define NTILE (HH*MD)               // 1152 (i,j) tiles
#define UPT   12                    // units per tile (1 unit = 6 m-steps = 2 triples)
#define NUNITS (NTILE*UPT)          // 13824 work units
#define GRID 1776                   // 2x oversubscription of 888 resident CTAs
#define S_I  3538944LL              // MD*HH*MD*64 floats
#define S_J  73728LL                // HH*MD*64 floats

__device__ float        g_partials[GRID * 8];
__device__ unsigned int g_count = 0;
__device__ __align__(16) float g_bs[NTILE];    // sig4[l]*phi_t[k,l]
__device__ __align__(16) float g_cij[NTILE];   // lam4[i]*phi[j,i]
__device__ __align__(16) float g_w3[NTILE];    // sig4[l]*phi_t[k,l] at (l,k)=(i,j) -- term3 weight

// L2 cache-hint load (policy in register)
__device__ __forceinline__ float4 ldg_pol(const float4* p, unsigned long long pol) {
    float4 v;
    asm("ld.global.cg.L2::cache_hint.v4.f32 {%0,%1,%2,%3}, [%4], %5;"
        : "=f"(v.x), "=f"(v.y), "=f"(v.z), "=f"(v.w)
        : "l"(p), "l"(pol));
    return v;
}

__global__ __launch_bounds__(256) void dsc_setup_kernel(
    const float* __restrict__ sigma,
    const float* __restrict__ lambda_e,
    const float* __restrict__ phi,
    const float* __restrict__ phi_tilde)
{
    __shared__ float sig4_sh[HH];
    __shared__ float lam4_sh[HH];
    const int tid = threadIdx.x;
    if (tid < HH) {
        sig4_sh[tid] = sqrtf(sqrtf(sigma[tid]));
        lam4_sh[tid] = sqrtf(sqrtf(lambda_e[tid]));
    }
    __syncthreads();
    for (int e = tid; e < NTILE; e += 256) {
        int a = e / 48;                          // l (or i)
        int b = e - a * 48;                      // k (or j)
        float w = sig4_sh[a] * phi_tilde[b * HH + a];
        g_bs[e]  = w;
        g_w3[e]  = w;                            // same formula, indexed by (i,j) tile
        g_cij[e] = lam4_sh[a] * phi[b * HH + a];
    }
}

__global__ __launch_bounds__(256, 6) void dsc_main_kernel(
    const float* __restrict__ y_rev,
    const float* __restrict__ M_tilde,
    const float* __restrict__ M,
    float* __restrict__ out)
{
    __shared__ __align__(16) float bs_sh[NTILE];      // 4.5 KB
    __shared__ __align__(16) float y_sh[96 * 8];      // 3 KB
    __shared__ float red_sh[8 * 8];
    __shared__ int   last_flag;

    const int tid = threadIdx.x;

    // cheap prologue: two vector copies (all L2-resident after first CTA)
    {
        const float4* ys = reinterpret_cast<const float4*>(y_rev);
        float4* yd = reinterpret_cast<float4*>(y_sh);
        for (int e = tid; e < 192; e += 256) yd[e] = ys[e];
        const float4* bsrc = reinterpret_cast<const float4*>(g_bs);
        float4* bdst = reinterpret_cast<float4*>(bs_sh);
        for (int e = tid; e < NTILE / 4; e += 256) bdst[e] = bsrc[e];
    }
    __syncthreads();

    // static balanced unit range (deterministic)
    const int q = NUNITS / GRID;                 // 7
    const int r = NUNITS % GRID;                 // 1392
    const int b = blockIdx.x;
    const int ustart = b * q + (b < r ? b : r);
    const int uend   = ustart + q + (b < r ? 1 : 0);

    const int lane  = tid & 31;
    const int warp  = tid >> 5;
    const int half  = lane >> 4;
    const int off16 = lane & 15;
    const int pbase = (off16 & 1) << 2;
    const int ysel  = off16 & 1;
    const int t0    = warp * 2 + half;           // 0..15

    const float4* __restrict__ yv4 = reinterpret_cast<const float4*>(y_sh);

    float4 acc  = make_float4(0.f, 0.f, 0.f, 0.f);   // running (c,p) partial
    float4 accA = make_float4(0.f, 0.f, 0.f, 0.f);   // per-tile phase sums
    float4 accB = make_float4(0.f, 0.f, 0.f, 0.f);
    float4 accC = make_float4(0.f, 0.f, 0.f, 0.f);

    int u = ustart;
    while (u < uend) {
        const int tl  = u / UPT;
        const int r12 = u - tl * UPT;
        const int ti  = tl / MD;
        const int tj  = tl - ti * MD;
        const float c_ij = __ldg(&g_cij[tl]);

        // L2 policy: persist a fixed ~29% stripe across graph replays
        unsigned long long pol;
        if ((tl % 24) < 7)
            asm("createpolicy.fractional.L2::evict_last.b64 %0, 1.0;" : "=l"(pol));
        else
            asm("createpolicy.fractional.L2::evict_first.b64 %0, 1.0;" : "=l"(pol));

        // owner of tile's first unit folds the small terms (terms 2 and 3)
        if (r12 == 0 && warp < 2 && half == 0) {
            const float* src;
            float w2;
            if (warp == 0) {
                src = M_tilde + (size_t)tl * 64;
                w2  = c_ij;
            } else {
                src = M + (size_t)ti * S_I + (size_t)tj * S_J;   // M[l,k,0,0,:,:]
                w2  = __ldg(&g_w3[tl]);
            }
            float4 mv = *reinterpret_cast<const float4*>(src + off16 * 4);
            const float* yb = &y_sh[tj * 8 + pbase];
            acc.x = fmaf(mv.x, w2 * yb[0], acc.x);
            acc.y = fmaf(mv.y, w2 * yb[1], acc.y);
            acc.z = fmaf(mv.z, w2 * yb[2], acc.z);
            acc.w = fmaf(mv.w, w2 * yb[3], acc.w);
        }

        const int ustop = min(uend, (tl + 1) * UPT);
        const int ntrip = (ustop - u) * 2;       // triples in this run

        const float4* __restrict__ p =
            reinterpret_cast<const float4*>(M + (size_t)tl * S_J)
            + (size_t)(t0 + r12 * 96) * 16 + off16;
        int tb = t0 + r12 * 96;

        #pragma unroll 2
        for (int it = 0; it < ntrip; ++it) {
            float4 m0 = ldg_pol(p,       pol);
            float4 m1 = ldg_pol(p + 256, pol);
            float4 m2 = ldg_pol(p + 512, pol);
            float w0 = bs_sh[tb];
            float w1 = bs_sh[tb + 16];
            float w2 = bs_sh[tb + 32];
            accA.x = fmaf(m0.x, w0, accA.x);
            accA.y = fmaf(m0.y, w0, accA.y);
            accA.z = fmaf(m0.z, w0, accA.z);
            accA.w = fmaf(m0.w, w0, accA.w);
            accB.x = fmaf(m1.x, w1, accB.x);
            accB.y = fmaf(m1.y, w1, accB.y);
            accB.z = fmaf(m1.z, w1, accB.z);
            accB.w = fmaf(m1.w, w1, accB.w);
            accC.x = fmaf(m2.x, w2, accC.x);
            accC.y = fmaf(m2.y, w2, accC.y);
            accC.z = fmaf(m2.z, w2, accC.z);
            accC.w = fmaf(m2.w, w2, accC.w);
            p  += 768;
            tb += 48;
        }

        // tile epilogue: fold y and c_ij into the running accumulator
        {
            const float4 yA = yv4[(tj + t0     ) * 2 + ysel];
            const float4 yB = yv4[(tj + t0 + 16) * 2 + ysel];
            const float4 yC = yv4[(tj + t0 + 32) * 2 + ysel];
            acc.x = fmaf(c_ij * yA.x, accA.x, acc.x);
            acc.y = fmaf(c_ij * yA.y, accA.y, acc.y);
            acc.z = fmaf(c_ij * yA.z, accA.z, acc.z);
            acc.w = fmaf(c_ij * yA.w, accA.w, acc.w);
            acc.x = fmaf(c_ij * yB.x, accB.x, acc.x);
            acc.y = fmaf(c_ij * yB.y, accB.y, acc.y);
            acc.z = fmaf(c_ij * yB.z, accB.z, acc.z);
            acc.w = fmaf(c_ij * yB.w, accB.w, acc.w);
            acc.x = fmaf(c_ij * yC.x, accC.x, acc.x);
            acc.y = fmaf(c_ij * yC.y, accC.y, acc.y);
            acc.z = fmaf(c_ij * yC.z, accC.z, acc.z);
            acc.w = fmaf(c_ij * yC.w, accC.w, acc.w);
            accA = make_float4(0.f, 0.f, 0.f, 0.f);
            accB = make_float4(0.f, 0.f, 0.f, 0.f);
            accC = make_float4(0.f, 0.f, 0.f, 0.f);
        }
        u = ustop;
    }

    // block reduction: lane partial for channel c = off16>>1
    float s = acc.x + acc.y + acc.z + acc.w;
    s += __shfl_xor_sync(0xffffffffu, s, 16);
    s += __shfl_xor_sync(0xffffffffu, s, 1);
    if (half == 0 && (off16 & 1) == 0)
        red_sh[warp * 8 + (off16 >> 1)] = s;
    __syncthreads();

    if (tid < 8) {
        float rr = 0.f;
        #pragma unroll
        for (int w = 0; w < 8; ++w) rr += red_sh[w * 8 + tid];
        g_partials[blockIdx.x * 8 + tid] = rr;
    }
    __syncthreads();

    // last-block-done final reduction (deterministic fixed order)
    if (tid == 0) {
        __threadfence();
        unsigned int prev = atomicAdd(&g_count, 1u);
        last_flag = (prev == GRID - 1u);
    }
    __syncthreads();

    if (last_flag) {
        __threadfence();
        float rr = 0.f;
        for (int bb = lane; bb < GRID; bb += 32)
            rr += g_partials[bb * 8 + warp];
        #pragma unroll
        for (int d = 16; d > 0; d >>= 1)
            rr += __shfl_xor_sync(0xffffffffu, rr, d);
        if (lane == 0) {
            float t1 = 0.f;
            #pragma unroll
            for (int p2 = 0; p2 < 8; ++p2)
                t1 += M_tilde[warp * 8 + p2] * y_sh[p2];   // term1
            out[warp] = rr + t1;
        }
        if (tid == 0) g_count = 0;   // re-arm for graph replay
    }
}

extern "C" void kernel_launch(void* const* d_in, const int* in_sizes, int n_in,
                              void* d_out, int out_size)
{
    const float* y_rev     = (const float*)d_in[0];
    const float* M_tilde   = (const float*)d_in[1];
    const float* M         = (const float*)d_in[2];
    const float* sigma     = (const float*)d_in[3];
    const float* lambda_e  = (const float*)d_in[4];
    const float* phi       = (const float*)d_in[5];
    const float* phi_tilde = (const float*)d_in[6];
    float* out = (float*)d_out;

    dsc_setup_kernel<<<1, 256>>>(sigma, lambda_e, phi, phi_tilde);
    dsc_main_kernel<<<GRID, 256>>>(y_rev, M_tilde, M, out);
}

// round 10
// speedup vs baseline: 1.0041x; 1.0041x over previous
#include <cuda_runtime.h>
#include <math.h>

// Shapes: H=24, Mdim=48, C=8, P=8
// u[c] = term1 + term2 + term3 + term4 (see previous rounds)

#define HH 24
#define MD 48
#define NTILE (HH*MD)               // 1152 (i,j) tiles
#define UPT   24                    // units per tile (1 unit = 1 triple = 3 m-steps)
#define NUNITS (NTILE*UPT)          // 27648 work units
#define GRID 888                    // 148 SMs x 6 CTAs -> single wave
#define S_I  3538944LL              // MD*HH*MD*64 floats
#define S_J  73728LL                // HH*MD*64 floats

__device__ float        g_partials[GRID * 8];
__device__ unsigned int g_count = 0;

// L2 cache-hint load (policy in register)
__device__ __forceinline__ float4 ldg_pol(const float4* p, unsigned long long pol) {
    float4 v;
    asm("ld.global.cg.L2::cache_hint.v4.f32 {%0,%1,%2,%3}, [%4], %5;"
        : "=f"(v.x), "=f"(v.y), "=f"(v.z), "=f"(v.w)
        : "l"(p), "l"(pol));
    return v;
}

__global__ __launch_bounds__(256, 6) void dsc_main_kernel(
    const float* __restrict__ y_rev,
    const float* __restrict__ M_tilde,
    const float* __restrict__ M,
    const float* __restrict__ sigma,
    const float* __restrict__ lambda_e,
    const float* __restrict__ phi,
    const float* __restrict__ phi_tilde,
    float* __restrict__ out)
{
    __shared__ __align__(16) float bs_sh[NTILE];      // sig4[l]*phi_t[k,l]  (tile-invariant)
    __shared__ __align__(16) float y_sh[96 * 8];
    __shared__ __align__(16) float phit_sh[MD * HH];
    __shared__ float sig4_sh[HH];
    __shared__ float lam4_sh[HH];
    __shared__ float red_sh[8 * 8];
    __shared__ int   last_flag;

    const int tid = threadIdx.x;

    for (int e = tid; e < 96 * 8; e += 256) y_sh[e] = y_rev[e];
    for (int e = tid; e < MD * HH; e += 256) phit_sh[e] = phi_tilde[e];
    if (tid < HH) {
        sig4_sh[tid] = sqrtf(sqrtf(sigma[tid]));
        lam4_sh[tid] = sqrtf(sqrtf(lambda_e[tid]));
    }
    __syncthreads();
    for (int e = tid; e < NTILE; e += 256) {
        int l = e / 48;
        int k = e - l * 48;
        bs_sh[e] = sig4_sh[l] * phit_sh[k * HH + l];
    }
    __syncthreads();

    // static balanced unit range (deterministic)
    const int q = NUNITS / GRID;                 // 31
    const int r = NUNITS % GRID;                 // 120
    const int b = blockIdx.x;
    const int ustart = b * q + (b < r ? b : r);
    const int uend   = ustart + q + (b < r ? 1 : 0);

    const int lane  = tid & 31;
    const int warp  = tid >> 5;
    const int half  = lane >> 4;
    const int off16 = lane & 15;
    const int pbase = (off16 & 1) << 2;
    const int ysel  = off16 & 1;
    const int t0    = warp * 2 + half;           // 0..15

    const float4* __restrict__ yv4 = reinterpret_cast<const float4*>(y_sh);

    float4 acc  = make_float4(0.f, 0.f, 0.f, 0.f);   // running (c,p) partial
    float4 accA = make_float4(0.f, 0.f, 0.f, 0.f);   // per-tile phase sums
    float4 accB = make_float4(0.f, 0.f, 0.f, 0.f);
    float4 accC = make_float4(0.f, 0.f, 0.f, 0.f);

    int u = ustart;
    while (u < uend) {
        const int tl  = u / UPT;
        const int r24 = u - tl * UPT;            // starting triple within tile
        const int ti  = tl / MD;
        const int tj  = tl - ti * MD;
        const float c_ij = lam4_sh[ti] * __ldg(&phi[tj * HH + ti]);

        // L2 policy: persist a fixed ~33% stripe (113 MB) across graph replays
        unsigned long long pol;
        if ((tl % 24) < 8)
            asm("createpolicy.fractional.L2::evict_last.b64 %0, 1.0;" : "=l"(pol));
        else
            asm("createpolicy.fractional.L2::evict_first.b64 %0, 1.0;" : "=l"(pol));

        // owner of tile's first unit folds the small terms (terms 2 and 3)
        if (r24 == 0 && warp < 2 && half == 0) {
            const float* src;
            float w2;
            if (warp == 0) {
                src = M_tilde + (size_t)tl * 64;
                w2  = c_ij;
            } else {
                src = M + (size_t)ti * S_I + (size_t)tj * S_J;   // M[l,k,0,0,:,:]
                w2  = sig4_sh[ti] * phit_sh[tj * HH + ti];
            }
            float4 mv = *reinterpret_cast<const float4*>(src + off16 * 4);
            const float* yb = &y_sh[tj * 8 + pbase];
            acc.x = fmaf(mv.x, w2 * yb[0], acc.x);
            acc.y = fmaf(mv.y, w2 * yb[1], acc.y);
            acc.z = fmaf(mv.z, w2 * yb[2], acc.z);
            acc.w = fmaf(mv.w, w2 * yb[3], acc.w);
        }

        const int ustop = min(uend, (tl + 1) * UPT);
        const int ntrip = ustop - u;             // triples in this run (1..24)

        const float4* __restrict__ p =
            reinterpret_cast<const float4*>(M + (size_t)tl * S_J)
            + (size_t)(t0 + r24 * 48) * 16 + off16;
        int tb = t0 + r24 * 48;

        #pragma unroll 2
        for (int it = 0; it < ntrip; ++it) {
            float4 m0 = ldg_pol(p,       pol);
            float4 m1 = ldg_pol(p + 256, pol);
            float4 m2 = ldg_pol(p + 512, pol);
            float w0 = bs_sh[tb];
            float w1 = bs_sh[tb + 16];
            float w2 = bs_sh[tb + 32];
            accA.x = fmaf(m0.x, w0, accA.x);
            accA.y = fmaf(m0.y, w0, accA.y);
            accA.z = fmaf(m0.z, w0, accA.z);
            accA.w = fmaf(m0.w, w0, accA.w);
            accB.x = fmaf(m1.x, w1, accB.x);
            accB.y = fmaf(m1.y, w1, accB.y);
            accB.z = fmaf(m1.z, w1, accB.z);
            accB.w = fmaf(m1.w, w1, accB.w);
            accC.x = fmaf(m2.x, w2, accC.x);
            accC.y = fmaf(m2.y, w2, accC.y);
            accC.z = fmaf(m2.z, w2, accC.z);
            accC.w = fmaf(m2.w, w2, accC.w);
            p  += 768;
            tb += 48;
        }

        // tile epilogue: fold y and c_ij into the running accumulator
        {
            const float4 yA = yv4[(tj + t0     ) * 2 + ysel];
            const float4 yB = yv4[(tj + t0 + 16) * 2 + ysel];
            const float4 yC = yv4[(tj + t0 + 32) * 2 + ysel];
            acc.x = fmaf(c_ij * yA.x, accA.x, acc.x);
            acc.y = fmaf(c_ij * yA.y, accA.y, acc.y);
            acc.z = fmaf(c_ij * yA.z, accA.z, acc.z);
            acc.w = fmaf(c_ij * yA.w, accA.w, acc.w);
            acc.x = fmaf(c_ij * yB.x, accB.x, acc.x);
            acc.y = fmaf(c_ij * yB.y, accB.y, acc.y);
            acc.z = fmaf(c_ij * yB.z, accB.z, acc.z);
            acc.w = fmaf(c_ij * yB.w, accB.w, acc.w);
            acc.x = fmaf(c_ij * yC.x, accC.x, acc.x);
            acc.y = fmaf(c_ij * yC.y, accC.y, acc.y);
            acc.z = fmaf(c_ij * yC.z, accC.z, acc.z);
            acc.w = fmaf(c_ij * yC.w, accC.w, acc.w);
            accA = make_float4(0.f, 0.f, 0.f, 0.f);
            accB = make_float4(0.f, 0.f, 0.f, 0.f);
            accC = make_float4(0.f, 0.f, 0.f, 0.f);
        }
        u = ustop;
    }

    // block reduction: lane partial for channel c = off16>>1
    float s = acc.x + acc.y + acc.z + acc.w;
    s += __shfl_xor_sync(0xffffffffu, s, 16);
    s += __shfl_xor_sync(0xffffffffu, s, 1);
    if (half == 0 && (off16 & 1) == 0)
        red_sh[warp * 8 + (off16 >> 1)] = s;
    __syncthreads();

    if (tid < 8) {
        float rr = 0.f;
        #pragma unroll
        for (int w = 0; w < 8; ++w) rr += red_sh[w * 8 + tid];
        g_partials[blockIdx.x * 8 + tid] = rr;
    }
    __syncthreads();

    // last-block-done final reduction (deterministic fixed order)
    if (tid == 0) {
        __threadfence();
        unsigned int prev = atomicAdd(&g_count, 1u);
        last_flag = (prev == GRID - 1u);
    }
    __syncthreads();

    if (last_flag) {
        __threadfence();
        float rr = 0.f;
        for (int bb = lane; bb < GRID; bb += 32)
            rr += g_partials[bb * 8 + warp];
        #pragma unroll
        for (int d = 16; d > 0; d >>= 1)
            rr += __shfl_xor_sync(0xffffffffu, rr, d);
        if (lane == 0 && warp < 8) {
            float t1 = 0.f;
            #pragma unroll
            for (int p2 = 0; p2 < 8; ++p2)
                t1 += M_tilde[warp * 8 + p2] * y_sh[p2];   // term1
            out[warp] = rr + t1;
        }
        if (tid == 0) g_count = 0;   // re-arm for graph replay
    }
}

extern "C" void kernel_launch(void* const* d_in, const int* in_sizes, int n_in,
                              void* d_out, int out_size)
{
    const float* y_rev     = (const float*)d_in[0];
    const float* M_tilde   = (const float*)d_in[1];
    const float* M         = (const float*)d_in[2];
    const float* sigma     = (const float*)d_in[3];
    const float* lambda_e  = (const float*)d_in[4];
    const float* phi       = (const float*)d_in[5];
    const float* phi_tilde = (const float*)d_in[6];
    float* out = (float*)d_out;

    dsc_main_kernel<<<GRID, 256>>>(y_rev, M_tilde, M, sigma, lambda_e,
                                   phi, phi_tilde, out);
}

// round 11
// speedup vs baseline: 1.0385x; 1.0342x over previous
#include <cuda_runtime.h>
#include <math.h>

// Shapes: H=24, Mdim=48, C=8, P=8
// u[c] = term1 + term2 + term3 + term4 (see previous rounds)

#define HH 24
#define MD 48
#define NTILE (HH*MD)               // 1152 (i,j) tiles
#define UPT   12                    // units per tile (1 unit = 6 m-steps = 2 triples)
#define NUNITS (NTILE*UPT)          // 13824 work units
#define GRID 888                    // 148 SMs x 6 CTAs -> single wave
#define S_I  3538944LL              // MD*HH*MD*64 floats
#define S_J  73728LL                // HH*MD*64 floats

__device__ float        g_partials[GRID * 8];
__device__ unsigned int g_count = 0;

// L2 cache-hint load (policy in register)
__device__ __forceinline__ float4 ldg_pol(const float4* p, unsigned long long pol) {
    float4 v;
    asm("ld.global.cg.L2::cache_hint.v4.f32 {%0,%1,%2,%3}, [%4], %5;"
        : "=f"(v.x), "=f"(v.y), "=f"(v.z), "=f"(v.w)
        : "l"(p), "l"(pol));
    return v;
}

__global__ __launch_bounds__(256, 6) void dsc_main_kernel(
    const float* __restrict__ y_rev,
    const float* __restrict__ M_tilde,
    const float* __restrict__ M,
    const float* __restrict__ sigma,
    const float* __restrict__ lambda_e,
    const float* __restrict__ phi,
    const float* __restrict__ phi_tilde,
    float* __restrict__ out)
{
    __shared__ __align__(16) float bs_sh[NTILE];      // sig4[l]*phi_t[k,l]  (tile-invariant)
    __shared__ __align__(16) float y_sh[96 * 8];
    __shared__ __align__(16) float phit_sh[MD * HH];
    __shared__ float sig4_sh[HH];
    __shared__ float lam4_sh[HH];
    __shared__ float red_sh[8 * 8];
    __shared__ int   last_flag;

    const int tid = threadIdx.x;

    // static balanced unit range (deterministic) -- computed first so we can
    // prefetch this block's first data BEFORE the prologue (hides the ramp)
    const int q = NUNITS / GRID;                 // 15
    const int r = NUNITS % GRID;                 // 504
    const int b = blockIdx.x;
    const int ustart = b * q + (b < r ? b : r);
    const int uend   = ustart + q + (b < r ? 1 : 0);

    const int lane  = tid & 31;
    const int warp  = tid >> 5;
    const int half  = lane >> 4;
    const int off16 = lane & 15;
    const int pbase = (off16 & 1) << 2;
    const int ysel  = off16 & 1;
    const int t0    = warp * 2 + half;           // 0..15

    // early L2 prefetch: first 3 iterations (9 loads) of this block's stream
    {
        const int tl0 = ustart / UPT;
        const int r0  = ustart - tl0 * UPT;
        const char* pf = reinterpret_cast<const char*>(
            reinterpret_cast<const float4*>(M + (size_t)tl0 * S_J)
            + (size_t)(t0 + r0 * 96) * 16 + off16);
        #pragma unroll
        for (int z = 0; z < 3; ++z) {
            asm volatile("prefetch.global.L2 [%0];"    :: "l"(pf          ));
            asm volatile("prefetch.global.L2 [%0];"    :: "l"(pf +  4096  ));
            asm volatile("prefetch.global.L2 [%0];"    :: "l"(pf +  8192  ));
            pf += 12288;                          // 768 float4 = next iteration
        }
    }

    for (int e = tid; e < 96 * 8; e += 256) y_sh[e] = y_rev[e];
    for (int e = tid; e < MD * HH; e += 256) phit_sh[e] = phi_tilde[e];
    if (tid < HH) {
        sig4_sh[tid] = sqrtf(sqrtf(sigma[tid]));
        lam4_sh[tid] = sqrtf(sqrtf(lambda_e[tid]));
    }
    __syncthreads();
    for (int e = tid; e < NTILE; e += 256) {
        int l = e / 48;
        int k = e - l * 48;
        bs_sh[e] = sig4_sh[l] * phit_sh[k * HH + l];
    }
    __syncthreads();

    const float4* __restrict__ yv4 = reinterpret_cast<const float4*>(y_sh);

    float4 acc  = make_float4(0.f, 0.f, 0.f, 0.f);   // running (c,p) partial
    float4 accA = make_float4(0.f, 0.f, 0.f, 0.f);   // per-tile phase sums
    float4 accB = make_float4(0.f, 0.f, 0.f, 0.f);
    float4 accC = make_float4(0.f, 0.f, 0.f, 0.f);

    int u = ustart;
    while (u < uend) {
        const int tl  = u / UPT;
        const int r12 = u - tl * UPT;
        const int ti  = tl / MD;
        const int tj  = tl - ti * MD;
        const float c_ij = lam4_sh[ti] * __ldg(&phi[tj * HH + ti]);

        // L2 policy: persist a fixed ~29% stripe across graph replays
        unsigned long long pol;
        if ((tl % 24) < 7)
            asm("createpolicy.fractional.L2::evict_last.b64 %0, 1.0;" : "=l"(pol));
        else
            asm("createpolicy.fractional.L2::evict_first.b64 %0, 1.0;" : "=l"(pol));

        // owner of tile's first unit folds the small terms (terms 2 and 3)
        if (r12 == 0 && warp < 2 && half == 0) {
            const float* src;
            float w2;
            if (warp == 0) {
                src = M_tilde + (size_t)tl * 64;
                w2  = c_ij;
            } else {
                src = M + (size_t)ti * S_I + (size_t)tj * S_J;   // M[l,k,0,0,:,:]
                w2  = sig4_sh[ti] * phit_sh[tj * HH + ti];
            }
            float4 mv = *reinterpret_cast<const float4*>(src + off16 * 4);
            const float* yb = &y_sh[tj * 8 + pbase];
            acc.x = fmaf(mv.x, w2 * yb[0], acc.x);
            acc.y = fmaf(mv.y, w2 * yb[1], acc.y);
            acc.z = fmaf(mv.z, w2 * yb[2], acc.z);
            acc.w = fmaf(mv.w, w2 * yb[3], acc.w);
        }

        const int ustop = min(uend, (tl + 1) * UPT);
        const int ntrip = (ustop - u) * 2;       // triples in this run

        const float4* __restrict__ p =
            reinterpret_cast<const float4*>(M + (size_t)tl * S_J)
            + (size_t)(t0 + r12 * 96) * 16 + off16;
        int tb = t0 + r12 * 96;

        #pragma unroll 2
        for (int it = 0; it < ntrip; ++it) {
            float4 m0 = ldg_pol(p,       pol);
            float4 m1 = ldg_pol(p + 256, pol);
            float4 m2 = ldg_pol(p + 512, pol);
            float w0 = bs_sh[tb];
            float w1 = bs_sh[tb + 16];
            float w2 = bs_sh[tb + 32];
            accA.x = fmaf(m0.x, w0, accA.x);
            accA.y = fmaf(m0.y, w0, accA.y);
            accA.z = fmaf(m0.z, w0, accA.z);
            accA.w = fmaf(m0.w, w0, accA.w);
            accB.x = fmaf(m1.x, w1, accB.x);
            accB.y = fmaf(m1.y, w1, accB.y);
            accB.z = fmaf(m1.z, w1, accB.z);
            accB.w = fmaf(m1.w, w1, accB.w);
            accC.x = fmaf(m2.x, w2, accC.x);
            accC.y = fmaf(m2.y, w2, accC.y);
            accC.z = fmaf(m2.z, w2, accC.z);
            accC.w = fmaf(m2.w, w2, accC.w);
            p  += 768;
            tb += 48;
        }

        // tile epilogue: fold y and c_ij into the running accumulator
        {
            const float4 yA = yv4[(tj + t0     ) * 2 + ysel];
            const float4 yB = yv4[(tj + t0 + 16) * 2 + ysel];
            const float4 yC = yv4[(tj + t0 + 32) * 2 + ysel];
            acc.x = fmaf(c_ij * yA.x, accA.x, acc.x);
            acc.y = fmaf(c_ij * yA.y, accA.y, acc.y);
            acc.z = fmaf(c_ij * yA.z, accA.z, acc.z);
            acc.w = fmaf(c_ij * yA.w, accA.w, acc.w);
            acc.x = fmaf(c_ij * yB.x, accB.x, acc.x);
            acc.y = fmaf(c_ij * yB.y, accB.y, acc.y);
            acc.z = fmaf(c_ij * yB.z, accB.z, acc.z);
            acc.w = fmaf(c_ij * yB.w, accB.w, acc.w);
            acc.x = fmaf(c_ij * yC.x, accC.x, acc.x);
            acc.y = fmaf(c_ij * yC.y, accC.y, acc.y);
            acc.z = fmaf(c_ij * yC.z, accC.z, acc.z);
            acc.w = fmaf(c_ij * yC.w, accC.w, acc.w);
            accA = make_float4(0.f, 0.f, 0.f, 0.f);
            accB = make_float4(0.f, 0.f, 0.f, 0.f);
            accC = make_float4(0.f, 0.f, 0.f, 0.f);
        }
        u = ustop;
    }

    // block reduction: lane partial for channel c = off16>>1
    float s = acc.x + acc.y + acc.z + acc.w;
    s += __shfl_xor_sync(0xffffffffu, s, 16);
    s += __shfl_xor_sync(0xffffffffu, s, 1);
    if (half == 0 && (off16 & 1) == 0)
        red_sh[warp * 8 + (off16 >> 1)] = s;
    __syncthreads();

    if (tid < 8) {
        float rr = 0.f;
        #pragma unroll
        for (int w = 0; w < 8; ++w) rr += red_sh[w * 8 + tid];
        g_partials[blockIdx.x * 8 + tid] = rr;
    }
    __syncthreads();

    // last-block-done final reduction (deterministic fixed order)
    if (tid == 0) {
        __threadfence();
        unsigned int prev = atomicAdd(&g_count, 1u);
        last_flag = (prev == GRID - 1u);
    }
    __syncthreads();

    if (last_flag) {
        __threadfence();
        float rr = 0.f;
        for (int bb = lane; bb < GRID; bb += 32)
            rr += g_partials[bb * 8 + warp];
        #pragma unroll
        for (int d = 16; d > 0; d >>= 1)
            rr += __shfl_xor_sync(0xffffffffu, rr, d);
        if (lane == 0 && warp < 8) {
            float t1 = 0.f;
            #pragma unroll
            for (int p2 = 0; p2 < 8; ++p2)
                t1 += M_tilde[warp * 8 + p2] * y_sh[p2];   // term1
            out[warp] = rr + t1;
        }
        if (tid == 0) g_count = 0;   // re-arm for graph replay
    }
}

extern "C" void kernel_launch(void* const* d_in, const int* in_sizes, int n_in,
                              void* d_out, int out_size)
{
    const float* y_rev     = (const float*)d_in[0];
    const float* M_tilde   = (const float*)d_in[1];
    const float* M         = (const float*)d_in[2];
    const float* sigma     = (const float*)d_in[3];
    const float* lambda_e  = (const float*)d_in[4];
    const float* phi       = (const float*)d_in[5];
    const float* phi_tilde = (const float*)d_in[6];
    float* out = (float*)d_out;

    dsc_main_kernel<<<GRID, 256>>>(y_rev, M_tilde, M, sigma, lambda_e,
                                   phi, phi_tilde, out);
}

// round 12
// speedup vs baseline: 1.0705x; 1.0308x over previous
#include <cuda_runtime.h>
#include <math.h>

// Shapes: H=24, Mdim=48, C=8, P=8
// u[c] = term1 + term2 + term3 + term4 (see previous rounds)

#define HH 24
#define MD 48
#define NTILE (HH*MD)               // 1152 (i,j) tiles
#define UPT   12                    // units per tile (1 unit = 6 m-steps = 2 triples)
#define NUNITS (NTILE*UPT)          // 13824 work units
#define GRID 888                    // 148 SMs x 6 CTAs -> single wave
#define S_I  3538944LL              // MD*HH*MD*64 floats
#define S_J  73728LL                // HH*MD*64 floats

__device__ float        g_partials[8 * GRID];   // channel-major: [c][block]
__device__ unsigned int g_count = 0;

// L2 cache-hint load (policy in register)
__device__ __forceinline__ float4 ldg_pol(const float4* p, unsigned long long pol) {
    float4 v;
    asm("ld.global.cg.L2::cache_hint.v4.f32 {%0,%1,%2,%3}, [%4], %5;"
        : "=f"(v.x), "=f"(v.y), "=f"(v.z), "=f"(v.w)
        : "l"(p), "l"(pol));
    return v;
}

__global__ __launch_bounds__(256, 6) void dsc_main_kernel(
    const float* __restrict__ y_rev,
    const float* __restrict__ M_tilde,
    const float* __restrict__ M,
    const float* __restrict__ sigma,
    const float* __restrict__ lambda_e,
    const float* __restrict__ phi,
    const float* __restrict__ phi_tilde,
    float* __restrict__ out)
{
    __shared__ __align__(16) float bs_sh[NTILE];      // sig4[l]*phi_t[k,l]  (tile-invariant)
    __shared__ __align__(16) float y_sh[96 * 8];
    __shared__ __align__(16) float phit_sh[MD * HH];
    __shared__ float sig4_sh[HH];
    __shared__ float lam4_sh[HH];
    __shared__ float red_sh[8 * 8];
    __shared__ int   last_flag;

    const int tid = threadIdx.x;

    for (int e = tid; e < 96 * 8; e += 256) y_sh[e] = y_rev[e];
    for (int e = tid; e < MD * HH; e += 256) phit_sh[e] = phi_tilde[e];
    if (tid < HH) {
        sig4_sh[tid] = sqrtf(sqrtf(sigma[tid]));
        lam4_sh[tid] = sqrtf(sqrtf(lambda_e[tid]));
    }
    __syncthreads();
    for (int e = tid; e < NTILE; e += 256) {
        int l = e / 48;
        int k = e - l * 48;
        bs_sh[e] = sig4_sh[l] * phit_sh[k * HH + l];
    }
    __syncthreads();

    // static balanced unit range (deterministic)
    const int q = NUNITS / GRID;                 // 15
    const int r = NUNITS % GRID;                 // 504
    const int b = blockIdx.x;
    const int ustart = b * q + (b < r ? b : r);
    const int uend   = ustart + q + (b < r ? 1 : 0);

    const int lane  = tid & 31;
    const int warp  = tid >> 5;
    const int half  = lane >> 4;
    const int off16 = lane & 15;
    const int pbase = (off16 & 1) << 2;
    const int ysel  = off16 & 1;
    const int t0    = warp * 2 + half;           // 0..15

    const float4* __restrict__ yv4 = reinterpret_cast<const float4*>(y_sh);

    float4 acc  = make_float4(0.f, 0.f, 0.f, 0.f);   // running (c,p) partial
    float4 accA = make_float4(0.f, 0.f, 0.f, 0.f);   // per-tile phase sums
    float4 accB = make_float4(0.f, 0.f, 0.f, 0.f);
    float4 accC = make_float4(0.f, 0.f, 0.f, 0.f);

    int u = ustart;
    while (u < uend) {
        const int tl  = u / UPT;
        const int r12 = u - tl * UPT;
        const int ti  = tl / MD;
        const int tj  = tl - ti * MD;
        const float c_ij = lam4_sh[ti] * __ldg(&phi[tj * HH + ti]);

        // L2 policy: persist a fixed ~29% stripe across graph replays
        unsigned long long pol;
        if ((tl % 24) < 7)
            asm("createpolicy.fractional.L2::evict_last.b64 %0, 1.0;" : "=l"(pol));
        else
            asm("createpolicy.fractional.L2::evict_first.b64 %0, 1.0;" : "=l"(pol));

        // owner of tile's first unit folds the small terms (terms 2 and 3)
        if (r12 == 0 && warp < 2 && half == 0) {
            const float* src;
            float w2;
            if (warp == 0) {
                src = M_tilde + (size_t)tl * 64;
                w2  = c_ij;
            } else {
                src = M + (size_t)ti * S_I + (size_t)tj * S_J;   // M[l,k,0,0,:,:]
                w2  = sig4_sh[ti] * phit_sh[tj * HH + ti];
            }
            float4 mv = *reinterpret_cast<const float4*>(src + off16 * 4);
            const float* yb = &y_sh[tj * 8 + pbase];
            acc.x = fmaf(mv.x, w2 * yb[0], acc.x);
            acc.y = fmaf(mv.y, w2 * yb[1], acc.y);
            acc.z = fmaf(mv.z, w2 * yb[2], acc.z);
            acc.w = fmaf(mv.w, w2 * yb[3], acc.w);
        }

        const int ustop = min(uend, (tl + 1) * UPT);
        const int ntrip = (ustop - u) * 2;       // triples in this run

        const float4* __restrict__ p =
            reinterpret_cast<const float4*>(M + (size_t)tl * S_J)
            + (size_t)(t0 + r12 * 96) * 16 + off16;
        int tb = t0 + r12 * 96;

        #pragma unroll 2
        for (int it = 0; it < ntrip; ++it) {
            float4 m0 = ldg_pol(p,       pol);
            float4 m1 = ldg_pol(p + 256, pol);
            float4 m2 = ldg_pol(p + 512, pol);
            float w0 = bs_sh[tb];
            float w1 = bs_sh[tb + 16];
            float w2 = bs_sh[tb + 32];
            accA.x = fmaf(m0.x, w0, accA.x);
            accA.y = fmaf(m0.y, w0, accA.y);
            accA.z = fmaf(m0.z, w0, accA.z);
            accA.w = fmaf(m0.w, w0, accA.w);
            accB.x = fmaf(m1.x, w1, accB.x);
            accB.y = fmaf(m1.y, w1, accB.y);
            accB.z = fmaf(m1.z, w1, accB.z);
            accB.w = fmaf(m1.w, w1, accB.w);
            accC.x = fmaf(m2.x, w2, accC.x);
            accC.y = fmaf(m2.y, w2, accC.y);
            accC.z = fmaf(m2.z, w2, accC.z);
            accC.w = fmaf(m2.w, w2, accC.w);
            p  += 768;
            tb += 48;
        }

        // tile epilogue: fold y and c_ij into the running accumulator
        {
            const float4 yA = yv4[(tj + t0     ) * 2 + ysel];
            const float4 yB = yv4[(tj + t0 + 16) * 2 + ysel];
            const float4 yC = yv4[(tj + t0 + 32) * 2 + ysel];
            acc.x = fmaf(c_ij * yA.x, accA.x, acc.x);
            acc.y = fmaf(c_ij * yA.y, accA.y, acc.y);
            acc.z = fmaf(c_ij * yA.z, accA.z, acc.z);
            acc.w = fmaf(c_ij * yA.w, accA.w, acc.w);
            acc.x = fmaf(c_ij * yB.x, accB.x, acc.x);
            acc.y = fmaf(c_ij * yB.y, accB.y, acc.y);
            acc.z = fmaf(c_ij * yB.z, accB.z, acc.z);
            acc.w = fmaf(c_ij * yB.w, accB.w, acc.w);
            acc.x = fmaf(c_ij * yC.x, accC.x, acc.x);
            acc.y = fmaf(c_ij * yC.y, accC.y, acc.y);
            acc.z = fmaf(c_ij * yC.z, accC.z, acc.z);
            acc.w = fmaf(c_ij * yC.w, accC.w, acc.w);
            accA = make_float4(0.f, 0.f, 0.f, 0.f);
            accB = make_float4(0.f, 0.f, 0.f, 0.f);
            accC = make_float4(0.f, 0.f, 0.f, 0.f);
        }
        u = ustop;
    }

    // block reduction: lane partial for channel c = off16>>1
    float s = acc.x + acc.y + acc.z + acc.w;
    s += __shfl_xor_sync(0xffffffffu, s, 16);
    s += __shfl_xor_sync(0xffffffffu, s, 1);
    if (half == 0 && (off16 & 1) == 0)
        red_sh[warp * 8 + (off16 >> 1)] = s;
    __syncthreads();

    if (tid < 8) {
        float rr = 0.f;
        #pragma unroll
        for (int w = 0; w < 8; ++w) rr += red_sh[w * 8 + tid];
        g_partials[tid * GRID + b] = rr;          // channel-major
    }
    __syncthreads();

    // last-block-done final reduction (deterministic fixed order)
    if (tid == 0) {
        __threadfence();
        unsigned int prev = atomicAdd(&g_count, 1u);
        last_flag = (prev == GRID - 1u);
    }
    __syncthreads();

    if (!last_flag) return;                       // free the SM slot early

    __threadfence();
    // warp w owns output channel w; coalesced sweep over 888 partials
    float rr = 0.f;
    const float* __restrict__ row = &g_partials[warp * GRID];
    for (int bb = lane; bb < GRID; bb += 32)
        rr += row[bb];
    #pragma unroll
    for (int d = 16; d > 0; d >>= 1)
        rr += __shfl_xor_sync(0xffffffffu, rr, d);
    if (lane == 0) {
        float t1 = 0.f;
        #pragma unroll
        for (int p2 = 0; p2 < 8; ++p2)
            t1 += M_tilde[warp * 8 + p2] * y_sh[p2];   // term1
        out[warp] = rr + t1;
    }
    if (tid == 0) g_count = 0;   // re-arm for graph replay
}

extern "C" void kernel_launch(void* const* d_in, const int* in_sizes, int n_in,
                              void* d_out, int out_size)
{
    const float* y_rev     = (const float*)d_in[0];
    const float* M_tilde   = (const float*)d_in[1];
    const float* M         = (const float*)d_in[2];
    const float* sigma     = (const float*)d_in[3];
    const float* lambda_e  = (const float*)d_in[4];
    const float* phi       = (const float*)d_in[5];
    const float* phi_tilde = (const float*)d_in[6];
    float* out = (float*)d_out;

    dsc_main_kernel<<<GRID, 256>>>(y_rev, M_tilde, M, sigma, lambda_e,
                                   phi, phi_tilde, out);
}

// round 13
// speedup vs baseline: 1.1102x; 1.0371x over previous
#include <cuda_runtime.h>
#include <math.h>

// Shapes: H=24, Mdim=48, C=8, P=8
// u[c] = term1 + term2 + term3 + term4 (see previous rounds)

#define HH 24
#define MD 48
#define NTILE (HH*MD)               // 1152 (i,j) tiles
#define UPT   12                    // units per tile (1 unit = 6 m-steps = 2 triples)
#define NUNITS (NTILE*UPT)          // 13824 work units
#define GRID 888                    // 148 SMs x 6 CTAs -> single wave
#define S_I  3538944LL              // MD*HH*MD*64 floats
#define S_J  73728LL                // HH*MD*64 floats

__device__ float        g_partials[8 * GRID];   // channel-major: [c][block]
__device__ unsigned int g_count = 0;

// L2 cache-hint load (policy in register)
__device__ __forceinline__ float4 ldg_pol(const float4* p, unsigned long long pol) {
    float4 v;
    asm("ld.global.cg.L2::cache_hint.v4.f32 {%0,%1,%2,%3}, [%4], %5;"
        : "=f"(v.x), "=f"(v.y), "=f"(v.z), "=f"(v.w)
        : "l"(p), "l"(pol));
    return v;
}

__global__ __launch_bounds__(256, 6) void dsc_main_kernel(
    const float* __restrict__ y_rev,
    const float* __restrict__ M_tilde,
    const float* __restrict__ M,
    const float* __restrict__ sigma,
    const float* __restrict__ lambda_e,
    const float* __restrict__ phi,
    const float* __restrict__ phi_tilde,
    float* __restrict__ out)
{
    __shared__ __align__(16) float bs_sh[NTILE];      // sig4[l]*phi_t[k,l]  (tile-invariant)
    __shared__ __align__(16) float y_sh[96 * 8];
    __shared__ __align__(16) float phit_sh[MD * HH];
    __shared__ float sig4_sh[HH];
    __shared__ float lam4_sh[HH];
    __shared__ float red_sh[8 * 8];
    __shared__ int   last_flag;

    const int tid = threadIdx.x;

    for (int e = tid; e < 96 * 8; e += 256) y_sh[e] = y_rev[e];
    for (int e = tid; e < MD * HH; e += 256) phit_sh[e] = phi_tilde[e];
    if (tid < HH) {
        sig4_sh[tid] = sqrtf(sqrtf(sigma[tid]));
        lam4_sh[tid] = sqrtf(sqrtf(lambda_e[tid]));
    }
    __syncthreads();
    for (int e = tid; e < NTILE; e += 256) {
        int l = e / 48;
        int k = e - l * 48;
        bs_sh[e] = sig4_sh[l] * phit_sh[k * HH + l];
    }
    __syncthreads();

    // static balanced unit range (deterministic)
    const int q = NUNITS / GRID;                 // 15
    const int r = NUNITS % GRID;                 // 504
    const int b = blockIdx.x;
    const int ustart = b * q + (b < r ? b : r);
    const int uend   = ustart + q + (b < r ? 1 : 0);

    const int lane  = tid & 31;
    const int warp  = tid >> 5;
    const int half  = lane >> 4;
    const int off16 = lane & 15;
    const int pbase = (off16 & 1) << 2;
    const int ysel  = off16 & 1;
    const int t0    = warp * 2 + half;           // 0..15

    const float4* __restrict__ yv4 = reinterpret_cast<const float4*>(y_sh);

    float4 acc  = make_float4(0.f, 0.f, 0.f, 0.f);   // running (c,p) partial
    float4 accA = make_float4(0.f, 0.f, 0.f, 0.f);   // per-tile phase sums
    float4 accB = make_float4(0.f, 0.f, 0.f, 0.f);
    float4 accC = make_float4(0.f, 0.f, 0.f, 0.f);

    int u = ustart;
    while (u < uend) {
        const int tl  = u / UPT;
        const int r12 = u - tl * UPT;
        const int ti  = tl / MD;
        const int tj  = tl - ti * MD;
        const float c_ij = lam4_sh[ti] * __ldg(&phi[tj * HH + ti]);

        // L2 policy: persist a fixed ~71 MB stripe (5/24 of M) across replays.
        // Smaller than R8's 7/24: keeps per-set persistent pressure ~56% so
        // evict_last lines actually survive the streaming traffic.
        unsigned long long pol;
        if ((tl % 24) < 5)
            asm("createpolicy.fractional.L2::evict_last.b64 %0, 1.0;" : "=l"(pol));
        else
            asm("createpolicy.fractional.L2::evict_first.b64 %0, 1.0;" : "=l"(pol));

        // owner of tile's first unit folds the small terms (terms 2 and 3)
        if (r12 == 0 && warp < 2 && half == 0) {
            const float* src;
            float w2;
            if (warp == 0) {
                src = M_tilde + (size_t)tl * 64;
                w2  = c_ij;
            } else {
                src = M + (size_t)ti * S_I + (size_t)tj * S_J;   // M[l,k,0,0,:,:]
                w2  = sig4_sh[ti] * phit_sh[tj * HH + ti];
            }
            float4 mv = *reinterpret_cast<const float4*>(src + off16 * 4);
            const float* yb = &y_sh[tj * 8 + pbase];
            acc.x = fmaf(mv.x, w2 * yb[0], acc.x);
            acc.y = fmaf(mv.y, w2 * yb[1], acc.y);
            acc.z = fmaf(mv.z, w2 * yb[2], acc.z);
            acc.w = fmaf(mv.w, w2 * yb[3], acc.w);
        }

        const int ustop = min(uend, (tl + 1) * UPT);
        const int ntrip = (ustop - u) * 2;       // triples in this run

        const float4* __restrict__ p =
            reinterpret_cast<const float4*>(M + (size_t)tl * S_J)
            + (size_t)(t0 + r12 * 96) * 16 + off16;
        int tb = t0 + r12 * 96;

        #pragma unroll 2
        for (int it = 0; it < ntrip; ++it) {
            float4 m0 = ldg_pol(p,       pol);
            float4 m1 = ldg_pol(p + 256, pol);
            float4 m2 = ldg_pol(p + 512, pol);
            float w0 = bs_sh[tb];
            float w1 = bs_sh[tb + 16];
            float w2 = bs_sh[tb + 32];
            accA.x = fmaf(m0.x, w0, accA.x);
            accA.y = fmaf(m0.y, w0, accA.y);
            accA.z = fmaf(m0.z, w0, accA.z);
            accA.w = fmaf(m0.w, w0, accA.w);
            accB.x = fmaf(m1.x, w1, accB.x);
            accB.y = fmaf(m1.y, w1, accB.y);
            accB.z = fmaf(m1.z, w1, accB.z);
            accB.w = fmaf(m1.w, w1, accB.w);
            accC.x = fmaf(m2.x, w2, accC.x);
            accC.y = fmaf(m2.y, w2, accC.y);
            accC.z = fmaf(m2.z, w2, accC.z);
            accC.w = fmaf(m2.w, w2, accC.w);
            p  += 768;
            tb += 48;
        }

        // tile epilogue: fold y and c_ij into the running accumulator
        {
            const float4 yA = yv4[(tj + t0     ) * 2 + ysel];
            const float4 yB = yv4[(tj + t0 + 16) * 2 + ysel];
            const float4 yC = yv4[(tj + t0 + 32) * 2 + ysel];
            acc.x = fmaf(c_ij * yA.x, accA.x, acc.x);
            acc.y = fmaf(c_ij * yA.y, accA.y, acc.y);
            acc.z = fmaf(c_ij * yA.z, accA.z, acc.z);
            acc.w = fmaf(c_ij * yA.w, accA.w, acc.w);
            acc.x = fmaf(c_ij * yB.x, accB.x, acc.x);
            acc.y = fmaf(c_ij * yB.y, accB.y, acc.y);
            acc.z = fmaf(c_ij * yB.z, accB.z, acc.z);
            acc.w = fmaf(c_ij * yB.w, accB.w, acc.w);
            acc.x = fmaf(c_ij * yC.x, accC.x, acc.x);
            acc.y = fmaf(c_ij * yC.y, accC.y, acc.y);
            acc.z = fmaf(c_ij * yC.z, accC.z, acc.z);
            acc.w = fmaf(c_ij * yC.w, accC.w, acc.w);
            accA = make_float4(0.f, 0.f, 0.f, 0.f);
            accB = make_float4(0.f, 0.f, 0.f, 0.f);
            accC = make_float4(0.f, 0.f, 0.f, 0.f);
        }
        u = ustop;
    }

    // block reduction: lane partial for channel c = off16>>1
    float s = acc.x + acc.y + acc.z + acc.w;
    s += __shfl_xor_sync(0xffffffffu, s, 16);
    s += __shfl_xor_sync(0xffffffffu, s, 1);
    if (half == 0 && (off16 & 1) == 0)
        red_sh[warp * 8 + (off16 >> 1)] = s;
    __syncthreads();

    if (tid < 8) {
        float rr = 0.f;
        #pragma unroll
        for (int w = 0; w < 8; ++w) rr += red_sh[w * 8 + tid];
        g_partials[tid * GRID + b] = rr;          // channel-major
    }
    __syncthreads();

    // last-block-done final reduction (deterministic fixed order)
    if (tid == 0) {
        __threadfence();
        unsigned int prev = atomicAdd(&g_count, 1u);
        last_flag = (prev == GRID - 1u);
    }
    __syncthreads();

    if (!last_flag) return;                       // free the SM slot early

    __threadfence();
    // warp w owns output channel w; coalesced sweep over 888 partials
    float rr = 0.f;
    const float* __restrict__ row = &g_partials[warp * GRID];
    for (int bb = lane; bb < GRID; bb += 32)
        rr += row[bb];
    #pragma unroll
    for (int d = 16; d > 0; d >>= 1)
        rr += __shfl_xor_sync(0xffffffffu, rr, d);
    if (lane == 0) {
        float t1 = 0.f;
        #pragma unroll
        for (int p2 = 0; p2 < 8; ++p2)
            t1 += M_tilde[warp * 8 + p2] * y_sh[p2];   // term1
        out[warp] = rr + t1;
    }
    if (tid == 0) g_count = 0;   // re-arm for graph replay
}

extern "C" void kernel_launch(void* const* d_in, const int* in_sizes, int n_in,
                              void* d_out, int out_size)
{
    const float* y_rev     = (const float*)d_in[0];
    const float* M_tilde   = (const float*)d_in[1];
    const float* M         = (const float*)d_in[2];
    const float* sigma     = (const float*)d_in[3];
    const float* lambda_e  = (const float*)d_in[4];
    const float* phi       = (const float*)d_in[5];
    const float* phi_tilde = (const float*)d_in[6];
    float* out = (float*)d_out;

    dsc_main_kernel<<<GRID, 256>>>(y_rev, M_tilde, M, sigma, lambda_e,
                                   phi, phi_tilde, out);
}

// round 14
// speedup vs baseline: 1.1153x; 1.0046x over previous
#include <cuda_runtime.h>
#include <math.h>

// Shapes: H=24, Mdim=48, C=8, P=8
// u[c] = term1 + term2 + term3 + term4 (see previous rounds)

#define HH 24
#define MD 48
#define NTILE (HH*MD)               // 1152 (i,j) tiles
#define UPT   12                    // units per tile (1 unit = 6 m-steps = 2 triples)
#define NUNITS (NTILE*UPT)          // 13824 work units
#define GRID 888                    // 148 SMs x 6 CTAs -> single wave
#define S_I  3538944LL              // MD*HH*MD*64 floats
#define S_J  73728LL                // HH*MD*64 floats

__device__ float        g_partials[8 * GRID];   // channel-major: [c][block]
__device__ unsigned int g_count = 0;

// L2 cache-hint load (policy in register)
__device__ __forceinline__ float4 ldg_pol(const float4* p, unsigned long long pol) {
    float4 v;
    asm("ld.global.cg.L2::cache_hint.v4.f32 {%0,%1,%2,%3}, [%4], %5;"
        : "=f"(v.x), "=f"(v.y), "=f"(v.z), "=f"(v.w)
        : "l"(p), "l"(pol));
    return v;
}

__global__ __launch_bounds__(256, 6) void dsc_main_kernel(
    const float* __restrict__ y_rev,
    const float* __restrict__ M_tilde,
    const float* __restrict__ M,
    const float* __restrict__ sigma,
    const float* __restrict__ lambda_e,
    const float* __restrict__ phi,
    const float* __restrict__ phi_tilde,
    float* __restrict__ out)
{
    __shared__ __align__(16) float bs_sh[NTILE];      // sig4[l]*phi_t[k,l]  (tile-invariant)
    __shared__ __align__(16) float y_sh[96 * 8];
    __shared__ __align__(16) float phit_sh[MD * HH];
    __shared__ float sig4_sh[HH];
    __shared__ float lam4_sh[HH];
    __shared__ float red_sh[8 * 8];
    __shared__ int   last_flag;

    const int tid = threadIdx.x;

    for (int e = tid; e < 96 * 8; e += 256) y_sh[e] = y_rev[e];
    for (int e = tid; e < MD * HH; e += 256) phit_sh[e] = phi_tilde[e];
    if (tid < HH) {
        sig4_sh[tid] = sqrtf(sqrtf(sigma[tid]));
        lam4_sh[tid] = sqrtf(sqrtf(lambda_e[tid]));
    }
    __syncthreads();
    for (int e = tid; e < NTILE; e += 256) {
        int l = e / 48;
        int k = e - l * 48;
        bs_sh[e] = sig4_sh[l] * phit_sh[k * HH + l];
    }
    __syncthreads();

    // static balanced unit range (deterministic)
    const int q = NUNITS / GRID;                 // 15
    const int r = NUNITS % GRID;                 // 504
    const int b = blockIdx.x;
    const int ustart = b * q + (b < r ? b : r);
    const int uend   = ustart + q + (b < r ? 1 : 0);

    const int lane  = tid & 31;
    const int warp  = tid >> 5;
    const int half  = lane >> 4;
    const int off16 = lane & 15;
    const int pbase = (off16 & 1) << 2;
    const int ysel  = off16 & 1;
    const int t0    = warp * 2 + half;           // 0..15

    const float4* __restrict__ yv4 = reinterpret_cast<const float4*>(y_sh);

    float4 acc  = make_float4(0.f, 0.f, 0.f, 0.f);   // running (c,p) partial
    float4 accA = make_float4(0.f, 0.f, 0.f, 0.f);   // per-tile phase sums
    float4 accB = make_float4(0.f, 0.f, 0.f, 0.f);
    float4 accC = make_float4(0.f, 0.f, 0.f, 0.f);

    int u = ustart;
    while (u < uend) {
        const int tl  = u / UPT;
        const int r12 = u - tl * UPT;
        const int ti  = tl / MD;
        const int tj  = tl - ti * MD;
        const float c_ij = lam4_sh[ti] * __ldg(&phi[tj * HH + ti]);

        // L2 policy: persist a fixed ~57 MB stripe (4/24 of M) across replays.
        // Lower per-set persistent pressure (~45% of L2) -> higher retention
        // of evict_last lines under the streaming traffic.
        unsigned long long pol;
        if ((tl % 24) < 4)
            asm("createpolicy.fractional.L2::evict_last.b64 %0, 1.0;" : "=l"(pol));
        else
            asm("createpolicy.fractional.L2::evict_first.b64 %0, 1.0;" : "=l"(pol));

        // owner of tile's first unit folds the small terms (terms 2 and 3)
        if (r12 == 0 && warp < 2 && half == 0) {
            const float* src;
            float w2;
            if (warp == 0) {
                src = M_tilde + (size_t)tl * 64;
                w2  = c_ij;
            } else {
                src = M + (size_t)ti * S_I + (size_t)tj * S_J;   // M[l,k,0,0,:,:]
                w2  = sig4_sh[ti] * phit_sh[tj * HH + ti];
            }
            float4 mv = *reinterpret_cast<const float4*>(src + off16 * 4);
            const float* yb = &y_sh[tj * 8 + pbase];
            acc.x = fmaf(mv.x, w2 * yb[0], acc.x);
            acc.y = fmaf(mv.y, w2 * yb[1], acc.y);
            acc.z = fmaf(mv.z, w2 * yb[2], acc.z);
            acc.w = fmaf(mv.w, w2 * yb[3], acc.w);
        }

        const int ustop = min(uend, (tl + 1) * UPT);
        const int ntrip = (ustop - u) * 2;       // triples in this run

        const float4* __restrict__ p =
            reinterpret_cast<const float4*>(M + (size_t)tl * S_J)
            + (size_t)(t0 + r12 * 96) * 16 + off16;
        int tb = t0 + r12 * 96;

        #pragma unroll 2
        for (int it = 0; it < ntrip; ++it) {
            float4 m0 = ldg_pol(p,       pol);
            float4 m1 = ldg_pol(p + 256, pol);
            float4 m2 = ldg_pol(p + 512, pol);
            float w0 = bs_sh[tb];
            float w1 = bs_sh[tb + 16];
            float w2 = bs_sh[tb + 32];
            accA.x = fmaf(m0.x, w0, accA.x);
            accA.y = fmaf(m0.y, w0, accA.y);
            accA.z = fmaf(m0.z, w0, accA.z);
            accA.w = fmaf(m0.w, w0, accA.w);
            accB.x = fmaf(m1.x, w1, accB.x);
            accB.y = fmaf(m1.y, w1, accB.y);
            accB.z = fmaf(m1.z, w1, accB.z);
            accB.w = fmaf(m1.w, w1, accB.w);
            accC.x = fmaf(m2.x, w2, accC.x);
            accC.y = fmaf(m2.y, w2, accC.y);
            accC.z = fmaf(m2.z, w2, accC.z);
            accC.w = fmaf(m2.w, w2, accC.w);
            p  += 768;
            tb += 48;
        }

        // tile epilogue: fold y and c_ij into the running accumulator
        {
            const float4 yA = yv4[(tj + t0     ) * 2 + ysel];
            const float4 yB = yv4[(tj + t0 + 16) * 2 + ysel];
            const float4 yC = yv4[(tj + t0 + 32) * 2 + ysel];
            acc.x = fmaf(c_ij * yA.x, accA.x, acc.x);
            acc.y = fmaf(c_ij * yA.y, accA.y, acc.y);
            acc.z = fmaf(c_ij * yA.z, accA.z, acc.z);
            acc.w = fmaf(c_ij * yA.w, accA.w, acc.w);
            acc.x = fmaf(c_ij * yB.x, accB.x, acc.x);
            acc.y = fmaf(c_ij * yB.y, accB.y, acc.y);
            acc.z = fmaf(c_ij * yB.z, accB.z, acc.z);
            acc.w = fmaf(c_ij * yB.w, accB.w, acc.w);
            acc.x = fmaf(c_ij * yC.x, accC.x, acc.x);
            acc.y = fmaf(c_ij * yC.y, accC.y, acc.y);
            acc.z = fmaf(c_ij * yC.z, accC.z, acc.z);
            acc.w = fmaf(c_ij * yC.w, accC.w, acc.w);
            accA = make_float4(0.f, 0.f, 0.f, 0.f);
            accB = make_float4(0.f, 0.f, 0.f, 0.f);
            accC = make_float4(0.f, 0.f, 0.f, 0.f);
        }
        u = ustop;
    }

    // block reduction: lane partial for channel c = off16>>1
    float s = acc.x + acc.y + acc.z + acc.w;
    s += __shfl_xor_sync(0xffffffffu, s, 16);
    s += __shfl_xor_sync(0xffffffffu, s, 1);
    if (half == 0 && (off16 & 1) == 0)
        red_sh[warp * 8 + (off16 >> 1)] = s;
    __syncthreads();

    if (tid < 8) {
        float rr = 0.f;
        #pragma unroll
        for (int w = 0; w < 8; ++w) rr += red_sh[w * 8 + tid];
        g_partials[tid * GRID + b] = rr;          // channel-major
    }
    __syncthreads();

    // last-block-done final reduction (deterministic fixed order)
    if (tid == 0) {
        __threadfence();
        unsigned int prev = atomicAdd(&g_count, 1u);
        last_flag = (prev == GRID - 1u);
    }
    __syncthreads();

    if (!last_flag) return;                       // free the SM slot early

    __threadfence();
    // warp w owns output channel w; coalesced sweep over 888 partials
    float rr = 0.f;
    const float* __restrict__ row = &g_partials[warp * GRID];
    for (int bb = lane; bb < GRID; bb += 32)
        rr += row[bb];
    #pragma unroll
    for (int d = 16; d > 0; d >>= 1)
        rr += __shfl_xor_sync(0xffffffffu, rr, d);
    if (lane == 0) {
        float t1 = 0.f;
        #pragma unroll
        for (int p2 = 0; p2 < 8; ++p2)
            t1 += M_tilde[warp * 8 + p2] * y_sh[p2];   // term1
        out[warp] = rr + t1;
    }
    if (tid == 0) g_count = 0;   // re-arm for graph replay
}

extern "C" void kernel_launch(void* const* d_in, const int* in_sizes, int n_in,
                              void* d_out, int out_size)
{
    const float* y_rev     = (const float*)d_in[0];
    const float* M_tilde   = (const float*)d_in[1];
    const float* M         = (const float*)d_in[2];
    const float* sigma     = (const float*)d_in[3];
    const float* lambda_e  = (const float*)d_in[4];
    const float* phi       = (const float*)d_in[5];
    const float* phi_tilde = (const float*)d_in[6];
    float* out = (float*)d_out;

    dsc_main_kernel<<<GRID, 256>>>(y_rev, M_tilde, M, sigma, lambda_e,
                                   phi, phi_tilde, out);
}